// round 1
// baseline (speedup 1.0000x reference)
#include <cuda_runtime.h>
#include <math.h>
#include <stddef.h>

#define NH     20
#define DH     64
#define DMODEL 1280
#define SEQ    2048
#define BATCH  2

// Scratch (no allocation allowed -> __device__ globals)
__device__ float g_Q[BATCH * NH * SEQ * DH];
__device__ float g_K[BATCH * NH * SEQ * DH];
__device__ float g_V[BATCH * NH * SEQ * DH];
__device__ float g_attn[BATCH * SEQ * DMODEL];

// ---------------------------------------------------------------------------
// Tiled SGEMM: C[M,N] = A[M,K] @ B[K,N]
// BM=BN=128, BK=16, 256 threads, 8x8 per-thread microtile.
// MODE 0: A = arg (hidden states), epilogue scatters into g_Q/g_K/g_V head-major.
// MODE 1: A = g_attn (internal), epilogue adds bias and stores to C.
// ---------------------------------------------------------------------------
template <int MODE>
__global__ __launch_bounds__(256)
void sgemm_kernel(const float* __restrict__ A, const float* __restrict__ B,
                  const float* __restrict__ bias, float* __restrict__ C,
                  int M, int N, int K)
{
    __shared__ float As[16][128];   // transposed: As[k][m]
    __shared__ float Bs[16][128];   // natural:    Bs[k][n]

    const int t  = threadIdx.x;
    const int tx = t & 15;          // 0..15 -> col block
    const int ty = t >> 4;          // 0..15 -> row block
    const int m0 = blockIdx.y * 128;
    const int n0 = blockIdx.x * 128;

    const float* Ap = (MODE == 1) ? g_attn : A;

    float acc[8][8];
#pragma unroll
    for (int i = 0; i < 8; i++)
#pragma unroll
        for (int j = 0; j < 8; j++) acc[i][j] = 0.0f;

    const int arow = t >> 1;            // 0..127
    const int acol = (t & 1) * 8;       // 0 or 8
    const int brow = t >> 5;            // 0..7
    const int bcol = (t & 31) * 4;      // 0..124

    for (int k0 = 0; k0 < K; k0 += 16) {
        // global loads (registers)
        float4 a0 = *(const float4*)&Ap[(size_t)(m0 + arow) * K + k0 + acol];
        float4 a1 = *(const float4*)&Ap[(size_t)(m0 + arow) * K + k0 + acol + 4];
        float4 b0 = *(const float4*)&B[(size_t)(k0 + brow) * N + n0 + bcol];
        float4 b1 = *(const float4*)&B[(size_t)(k0 + brow + 8) * N + n0 + bcol];

        // smem stores
        As[acol + 0][arow] = a0.x; As[acol + 1][arow] = a0.y;
        As[acol + 2][arow] = a0.z; As[acol + 3][arow] = a0.w;
        As[acol + 4][arow] = a1.x; As[acol + 5][arow] = a1.y;
        As[acol + 6][arow] = a1.z; As[acol + 7][arow] = a1.w;
        *(float4*)&Bs[brow][bcol]     = b0;
        *(float4*)&Bs[brow + 8][bcol] = b1;
        __syncthreads();

#pragma unroll
        for (int kk = 0; kk < 16; kk++) {
            float a[8], bb[8];
            *(float4*)&a[0]  = *(const float4*)&As[kk][ty * 8];
            *(float4*)&a[4]  = *(const float4*)&As[kk][ty * 8 + 4];
            *(float4*)&bb[0] = *(const float4*)&Bs[kk][tx * 8];
            *(float4*)&bb[4] = *(const float4*)&Bs[kk][tx * 8 + 4];
#pragma unroll
            for (int i = 0; i < 8; i++)
#pragma unroll
                for (int j = 0; j < 8; j++)
                    acc[i][j] = fmaf(a[i], bb[j], acc[i][j]);
        }
        __syncthreads();
    }

    if (MODE == 0) {
        // scatter qkv columns into head-major [b][h][s][d] buffers
        const int part = n0 / DMODEL;            // 0=Q,1=K,2=V (BN=128 divides 1280)
        const int rem0 = n0 - part * DMODEL;
        float* base = (part == 0) ? g_Q : (part == 1) ? g_K : g_V;
#pragma unroll
        for (int i = 0; i < 8; i++) {
            const int r = m0 + ty * 8 + i;
            const int b = r >> 11;               // / 2048
            const int s = r & 2047;
#pragma unroll
            for (int jj = 0; jj < 8; jj += 4) {
                const int rem = rem0 + tx * 8 + jj;
                const int h = rem >> 6;
                const int d = rem & 63;          // multiple of 4
                float4 v = make_float4(acc[i][jj], acc[i][jj + 1],
                                       acc[i][jj + 2], acc[i][jj + 3]);
                *(float4*)&base[(((size_t)(b * NH + h)) * SEQ + s) * DH + d] = v;
            }
        }
    } else {
        float4 bv0 = *(const float4*)&bias[n0 + tx * 8];
        float4 bv1 = *(const float4*)&bias[n0 + tx * 8 + 4];
#pragma unroll
        for (int i = 0; i < 8; i++) {
            const int r = m0 + ty * 8 + i;
            float4 v0 = make_float4(acc[i][0] + bv0.x, acc[i][1] + bv0.y,
                                    acc[i][2] + bv0.z, acc[i][3] + bv0.w);
            float4 v1 = make_float4(acc[i][4] + bv1.x, acc[i][5] + bv1.y,
                                    acc[i][6] + bv1.z, acc[i][7] + bv1.w);
            *(float4*)&C[(size_t)r * N + n0 + tx * 8]     = v0;
            *(float4*)&C[(size_t)r * N + n0 + tx * 8 + 4] = v1;
        }
    }
}

// ---------------------------------------------------------------------------
// fp32 flash attention. Grid: (SEQ/64, BATCH*NH). 256 threads.
// CTA owns 64 queries of one (b,h). K-tiles of 64.
// Qt/Kt stored transposed [d][tok]; P reuses Kt's smem (union) as [q][k];
// V stored natural [k][d]. 48KB static smem total -> 4 CTAs/SM.
// ---------------------------------------------------------------------------
__global__ __launch_bounds__(256)
void flash_kernel(const float* __restrict__ mask)
{
    __shared__ float Qt[DH][64];     // [d][q]
    __shared__ float KtPt[64 * 64];  // Kt: [d][k]  /  Pt: [q][k] (union)
    __shared__ float Vs[64][64];     // [k][d]

    const int t  = threadIdx.x;
    const int tx = t & 15;           // 0..15
    const int ty = t >> 4;           // 0..15
    const int q0 = blockIdx.x * 64;
    const int bh = blockIdx.y;
    const int b  = bh / NH;
    const int h  = bh % NH;

    const float* Qg = g_Q + (size_t)bh * SEQ * DH;
    const float* Kg = g_K + (size_t)bh * SEQ * DH;
    const float* Vg = g_V + (size_t)bh * SEQ * DH;

    // Load Q tile transposed (row-spread mapping -> conflict-free STS)
    {
        const int row = t & 63;
        const int fb  = t >> 6;      // 0..3
#pragma unroll
        for (int c = 0; c < 4; c++) {
            const int f4 = fb * 4 + c;           // 0..15
            float4 v = *(const float4*)&Qg[(size_t)(q0 + row) * DH + f4 * 4];
            Qt[f4 * 4 + 0][row] = v.x; Qt[f4 * 4 + 1][row] = v.y;
            Qt[f4 * 4 + 2][row] = v.z; Qt[f4 * 4 + 3][row] = v.w;
        }
    }

    float m_i[4], l_i[4], o[4][4];
#pragma unroll
    for (int i = 0; i < 4; i++) {
        m_i[i] = -1e30f; l_i[i] = 0.0f;
#pragma unroll
        for (int j = 0; j < 4; j++) o[i][j] = 0.0f;
    }

    const float scl = 0.125f;  // 1/sqrt(64)

    for (int kt = 0; kt < SEQ; kt += 64) {
        // ---- load K (transposed) and V (natural) tiles ----
        {
            const int row = t & 63;
            const int fb  = t >> 6;
#pragma unroll
            for (int c = 0; c < 4; c++) {
                const int f4 = fb * 4 + c;
                float4 v = *(const float4*)&Kg[(size_t)(kt + row) * DH + f4 * 4];
                KtPt[(f4 * 4 + 0) * 64 + row] = v.x;
                KtPt[(f4 * 4 + 1) * 64 + row] = v.y;
                KtPt[(f4 * 4 + 2) * 64 + row] = v.z;
                KtPt[(f4 * 4 + 3) * 64 + row] = v.w;
            }
#pragma unroll
            for (int c = 0; c < 4; c++) {
                const int idx  = t + 256 * c;
                const int vrow = idx >> 4;
                const int vf4  = idx & 15;
                *(float4*)&Vs[vrow][vf4 * 4] =
                    *(const float4*)&Vg[(size_t)(kt + vrow) * DH + vf4 * 4];
            }
        }
        __syncthreads();   // (1) tiles ready

        // ---- scores: sc[i][j] = sum_d Q[q0+4ty+i][d] * K[kt+4tx+j][d] ----
        float sc[4][4];
#pragma unroll
        for (int i = 0; i < 4; i++)
#pragma unroll
            for (int j = 0; j < 4; j++) sc[i][j] = 0.0f;

#pragma unroll 8
        for (int d = 0; d < DH; d++) {
            float4 qa = *(const float4*)&Qt[d][ty * 4];
            float4 ka = *(const float4*)&KtPt[d * 64 + tx * 4];
            float qv[4] = {qa.x, qa.y, qa.z, qa.w};
            float kv[4] = {ka.x, ka.y, ka.z, ka.w};
#pragma unroll
            for (int i = 0; i < 4; i++)
#pragma unroll
                for (int j = 0; j < 4; j++)
                    sc[i][j] = fmaf(qv[i], kv[j], sc[i][j]);
        }

        // ---- scale + mask + row max (16-lane shuffle reduce) ----
        float mnew[4];
#pragma unroll
        for (int i = 0; i < 4; i++) {
            const int qg = q0 + ty * 4 + i;
            float4 mk = *(const float4*)&mask[((size_t)b * SEQ + qg) * SEQ + kt + tx * 4];
            sc[i][0] = fmaf(sc[i][0], scl, mk.x);
            sc[i][1] = fmaf(sc[i][1], scl, mk.y);
            sc[i][2] = fmaf(sc[i][2], scl, mk.z);
            sc[i][3] = fmaf(sc[i][3], scl, mk.w);
            float mx = fmaxf(fmaxf(sc[i][0], sc[i][1]), fmaxf(sc[i][2], sc[i][3]));
#pragma unroll
            for (int off = 8; off > 0; off >>= 1)
                mx = fmaxf(mx, __shfl_xor_sync(0xffffffffu, mx, off));
            mnew[i] = fmaxf(m_i[i], mx);
        }
        __syncthreads();   // (2) everyone done reading Kt -> can overwrite with P

        // ---- exp, running sum, write P into union smem ----
#pragma unroll
        for (int i = 0; i < 4; i++) {
            const float corr = __expf(m_i[i] - mnew[i]);
            float p0 = __expf(sc[i][0] - mnew[i]);
            float p1 = __expf(sc[i][1] - mnew[i]);
            float p2 = __expf(sc[i][2] - mnew[i]);
            float p3 = __expf(sc[i][3] - mnew[i]);
            *(float4*)&KtPt[(ty * 4 + i) * 64 + tx * 4] = make_float4(p0, p1, p2, p3);
            float rs = p0 + p1 + p2 + p3;
#pragma unroll
            for (int off = 8; off > 0; off >>= 1)
                rs += __shfl_xor_sync(0xffffffffu, rs, off);
            l_i[i] = l_i[i] * corr + rs;
            m_i[i] = mnew[i];
#pragma unroll
            for (int j = 0; j < 4; j++) o[i][j] *= corr;
        }
        __syncthreads();   // (3) P ready

        // ---- PV: o[i][j] += sum_k P[4ty+i][k] * V[k][4tx+j] ----
#pragma unroll 4
        for (int k = 0; k < 64; k += 4) {
            float pv[4][4], vv[4][4];
#pragma unroll
            for (int i = 0; i < 4; i++)
                *(float4*)pv[i] = *(const float4*)&KtPt[(ty * 4 + i) * 64 + k];
#pragma unroll
            for (int kk = 0; kk < 4; kk++)
                *(float4*)vv[kk] = *(const float4*)&Vs[k + kk][tx * 4];
#pragma unroll
            for (int i = 0; i < 4; i++)
#pragma unroll
                for (int kk = 0; kk < 4; kk++)
#pragma unroll
                    for (int j = 0; j < 4; j++)
                        o[i][j] = fmaf(pv[i][kk], vv[kk][j], o[i][j]);
        }
        __syncthreads();   // (4) done with P/V before next tile load
    }

    // ---- normalize and write attn output in [b][s][h*64+d] layout ----
#pragma unroll
    for (int i = 0; i < 4; i++) {
        const int qg = q0 + ty * 4 + i;
        const float inv = 1.0f / l_i[i];
        float4 v = make_float4(o[i][0] * inv, o[i][1] * inv,
                               o[i][2] * inv, o[i][3] * inv);
        *(float4*)&g_attn[((size_t)b * SEQ + qg) * DMODEL + h * DH + tx * 4] = v;
    }
}

// ---------------------------------------------------------------------------
extern "C" void kernel_launch(void* const* d_in, const int* in_sizes, int n_in,
                              void* d_out, int out_size)
{
    const float* x     = (const float*)d_in[0];  // [B,1,S,D]
    const float* mask  = (const float*)d_in[1];  // [B,1,S,S]
    const float* wqkv  = (const float*)d_in[2];  // [D,3D]
    const float* wout  = (const float*)d_in[3];  // [D,D]
    const float* bout  = (const float*)d_in[4];  // [D]
    float* out = (float*)d_out;                  // [B,1,S,D]

    (void)in_sizes; (void)n_in; (void)out_size;

    // 1) QKV projection, scattered into head-major scratch
    sgemm_kernel<0><<<dim3((3 * DMODEL) / 128, (BATCH * SEQ) / 128), 256>>>(
        x, wqkv, nullptr, nullptr, BATCH * SEQ, 3 * DMODEL, DMODEL);

    // 2) flash attention (fp32, online softmax)
    flash_kernel<<<dim3(SEQ / 64, BATCH * NH), 256>>>(mask);

    // 3) output projection + bias
    sgemm_kernel<1><<<dim3(DMODEL / 128, (BATCH * SEQ) / 128), 256>>>(
        nullptr, wout, bout, out, BATCH * SEQ, DMODEL, DMODEL);
}

// round 8
// speedup vs baseline: 1.3501x; 1.3501x over previous
#include <cuda_runtime.h>
#include <cstdint>
#include <math.h>
#include <stddef.h>

#define NH     20
#define DH     64
#define DMODEL 1280
#define SEQ    2048
#define BATCH  2

// Scratch (no allocation allowed -> __device__ globals)
__device__ float g_Q[BATCH * NH * SEQ * DH];
__device__ float g_K[BATCH * NH * SEQ * DH];
__device__ float g_V[BATCH * NH * SEQ * DH];
__device__ float g_attn[BATCH * SEQ * DMODEL];

// ---------------------------------------------------------------------------
__device__ __forceinline__ float to_tf32(float x) {
    uint32_t u = __float_as_uint(x), r;
    asm("cvt.rna.tf32.f32 %0, %1;" : "=r"(r) : "r"(u));
    return __uint_as_float(r);
}

// D += A*B, m16n8k8 tf32 (A row-major, B col-major fragments)
__device__ __forceinline__ void mma_tf32(float* c, const uint32_t* a, const uint32_t* b) {
    asm volatile(
        "mma.sync.aligned.m16n8k8.row.col.f32.tf32.tf32.f32 "
        "{%0,%1,%2,%3}, {%4,%5,%6,%7}, {%8,%9}, {%0,%1,%2,%3};"
        : "+f"(c[0]), "+f"(c[1]), "+f"(c[2]), "+f"(c[3])
        : "r"(a[0]), "r"(a[1]), "r"(a[2]), "r"(a[3]), "r"(b[0]), "r"(b[1]));
}

// ---------------------------------------------------------------------------
// tf32 mma.sync GEMM: C[M,N] = A[M,K] @ B[K,N]
// CTA 128x128, BK=32, double-buffered smem, 8 warps (warp tile 32x64).
// MODE 0: A = hidden states; epilogue scatters QKV head-major to g_Q/g_K/g_V.
// MODE 1: A = g_attn; epilogue adds bias, stores C.
// ---------------------------------------------------------------------------
#define ASTR 36    // padded floats per A row  (128 x 32 tile)
#define BSTR 132   // padded floats per B k-row (32 x 128 tile)
#define A_FLOATS (128 * ASTR)   // 4608
#define B_FLOATS (32 * BSTR)    // 4224
#define GEMM_SMEM ((2 * A_FLOATS + 2 * B_FLOATS) * 4)

template <int MODE>
__global__ __launch_bounds__(256)
void mma_gemm(const float* __restrict__ A, const float* __restrict__ B,
              const float* __restrict__ bias, float* __restrict__ C,
              int M, int N, int K)
{
    extern __shared__ float sm[];
    float* As[2] = { sm, sm + A_FLOATS };
    float* Bs[2] = { sm + 2 * A_FLOATS, sm + 2 * A_FLOATS + B_FLOATS };

    const int t    = threadIdx.x;
    const int lane = t & 31;
    const int wid  = t >> 5;
    const int g4   = lane >> 2;       // groupID (0..7)
    const int t4   = lane & 3;        // thread-in-group
    const int m0   = blockIdx.y * 128;
    const int n0   = blockIdx.x * 128;
    const int wm   = (wid & 3) * 32;  // warp m offset
    const int wn   = (wid >> 2) * 64; // warp n offset

    const float* Ap = (MODE == 1) ? g_attn : A;

    // gmem load assignments (fully coalesced 128B segments)
    const int am  = t >> 3;           // 0..31  (+ c*32)
    const int ak4 = t & 7;            // float4 index in k (0..7)
    const int bk  = t >> 3;           // 0..31 k-row
    const int bn4 = t & 7;            // float4 index in n (+ 8c)

    float cacc[2][8][4];
#pragma unroll
    for (int i = 0; i < 2; i++)
#pragma unroll
        for (int j = 0; j < 8; j++)
#pragma unroll
            for (int q = 0; q < 4; q++) cacc[i][j][q] = 0.0f;

    const int nk = K >> 5;  // BK = 32

    // ---- prologue: tile 0 ----
    {
        float4 ra[4], rb[4];
#pragma unroll
        for (int c = 0; c < 4; c++) {
            ra[c] = *(const float4*)&Ap[(size_t)(m0 + c * 32 + am) * K + ak4 * 4];
            rb[c] = *(const float4*)&B[(size_t)bk * N + n0 + (bn4 + 8 * c) * 4];
        }
#pragma unroll
        for (int c = 0; c < 4; c++) {
            float4 va = ra[c], vb = rb[c];
            va.x = to_tf32(va.x); va.y = to_tf32(va.y); va.z = to_tf32(va.z); va.w = to_tf32(va.w);
            vb.x = to_tf32(vb.x); vb.y = to_tf32(vb.y); vb.z = to_tf32(vb.z); vb.w = to_tf32(vb.w);
            *(float4*)&As[0][(c * 32 + am) * ASTR + ak4 * 4] = va;
            *(float4*)&Bs[0][bk * BSTR + (bn4 + 8 * c) * 4] = vb;
        }
    }
    __syncthreads();

    for (int kt = 0; kt < nk; kt++) {
        const int cur = kt & 1;
        float4 ra[4], rb[4];
        if (kt + 1 < nk) {
            const int k0 = (kt + 1) * 32;
#pragma unroll
            for (int c = 0; c < 4; c++) {
                ra[c] = *(const float4*)&Ap[(size_t)(m0 + c * 32 + am) * K + k0 + ak4 * 4];
                rb[c] = *(const float4*)&B[(size_t)(k0 + bk) * N + n0 + (bn4 + 8 * c) * 4];
            }
        }

        // ---- compute on buffer `cur` ----
        const float* Ab = As[cur];
        const float* Bb = Bs[cur];
#pragma unroll
        for (int ks = 0; ks < 4; ks++) {
            const int kk = ks * 8 + t4;
            uint32_t af[2][4], bf[8][2];
#pragma unroll
            for (int mt = 0; mt < 2; mt++) {
                const int r0 = wm + mt * 16 + g4;
                af[mt][0] = __float_as_uint(Ab[r0 * ASTR + kk]);
                af[mt][1] = __float_as_uint(Ab[(r0 + 8) * ASTR + kk]);
                af[mt][2] = __float_as_uint(Ab[r0 * ASTR + kk + 4]);
                af[mt][3] = __float_as_uint(Ab[(r0 + 8) * ASTR + kk + 4]);
            }
#pragma unroll
            for (int nt = 0; nt < 8; nt++) {
                const int nn = wn + nt * 8 + g4;
                bf[nt][0] = __float_as_uint(Bb[kk * BSTR + nn]);
                bf[nt][1] = __float_as_uint(Bb[(kk + 4) * BSTR + nn]);
            }
#pragma unroll
            for (int mt = 0; mt < 2; mt++)
#pragma unroll
                for (int nt = 0; nt < 8; nt++)
                    mma_tf32(cacc[mt][nt], af[mt], bf[nt]);
        }

        if (kt + 1 < nk) {
            const int nxt = (kt + 1) & 1;
#pragma unroll
            for (int c = 0; c < 4; c++) {
                float4 va = ra[c], vb = rb[c];
                va.x = to_tf32(va.x); va.y = to_tf32(va.y); va.z = to_tf32(va.z); va.w = to_tf32(va.w);
                vb.x = to_tf32(vb.x); vb.y = to_tf32(vb.y); vb.z = to_tf32(vb.z); vb.w = to_tf32(vb.w);
                *(float4*)&As[nxt][(c * 32 + am) * ASTR + ak4 * 4] = va;
                *(float4*)&Bs[nxt][bk * BSTR + (bn4 + 8 * c) * 4] = vb;
            }
        }
        __syncthreads();
    }

    // ---- epilogue ----
#pragma unroll
    for (int mt = 0; mt < 2; mt++) {
#pragma unroll
        for (int half = 0; half < 2; half++) {
            const int r = m0 + wm + mt * 16 + g4 + half * 8;
#pragma unroll
            for (int nt = 0; nt < 8; nt++) {
                const float v0 = cacc[mt][nt][half * 2 + 0];
                const float v1 = cacc[mt][nt][half * 2 + 1];
                const int ncol = wn + nt * 8 + t4 * 2;   // within CTA tile
                if (MODE == 0) {
                    const int gn   = n0 + ncol;
                    const int part = gn / DMODEL;        // 0=Q,1=K,2=V
                    const int rem  = gn - part * DMODEL;
                    float* base = (part == 0) ? g_Q : (part == 1) ? g_K : g_V;
                    const int h = rem >> 6, d = rem & 63;
                    const int b = r >> 11, s = r & 2047;
                    *(float2*)&base[(((size_t)(b * NH + h)) * SEQ + s) * DH + d] =
                        make_float2(v0, v1);
                } else {
                    const int gn = n0 + ncol;
                    *(float2*)&C[(size_t)r * N + gn] =
                        make_float2(v0 + bias[gn], v1 + bias[gn + 1]);
                }
            }
        }
    }
}

// ---------------------------------------------------------------------------
// fp32 flash attention (unchanged, known-good). Grid: (SEQ/64, BATCH*NH).
// ---------------------------------------------------------------------------
__global__ __launch_bounds__(256)
void flash_kernel(const float* __restrict__ mask)
{
    __shared__ float Qt[DH][64];     // [d][q]
    __shared__ float KtPt[64 * 64];  // Kt: [d][k]  /  Pt: [q][k] (union)
    __shared__ float Vs[64][64];     // [k][d]

    const int t  = threadIdx.x;
    const int tx = t & 15;
    const int ty = t >> 4;
    const int q0 = blockIdx.x * 64;
    const int bh = blockIdx.y;
    const int b  = bh / NH;
    const int h  = bh % NH;

    const float* Qg = g_Q + (size_t)bh * SEQ * DH;
    const float* Kg = g_K + (size_t)bh * SEQ * DH;
    const float* Vg = g_V + (size_t)bh * SEQ * DH;

    {
        const int row = t & 63;
        const int fb  = t >> 6;
#pragma unroll
        for (int c = 0; c < 4; c++) {
            const int f4 = fb * 4 + c;
            float4 v = *(const float4*)&Qg[(size_t)(q0 + row) * DH + f4 * 4];
            Qt[f4 * 4 + 0][row] = v.x; Qt[f4 * 4 + 1][row] = v.y;
            Qt[f4 * 4 + 2][row] = v.z; Qt[f4 * 4 + 3][row] = v.w;
        }
    }

    float m_i[4], l_i[4], o[4][4];
#pragma unroll
    for (int i = 0; i < 4; i++) {
        m_i[i] = -1e30f; l_i[i] = 0.0f;
#pragma unroll
        for (int j = 0; j < 4; j++) o[i][j] = 0.0f;
    }

    const float scl = 0.125f;

    for (int kt = 0; kt < SEQ; kt += 64) {
        {
            const int row = t & 63;
            const int fb  = t >> 6;
#pragma unroll
            for (int c = 0; c < 4; c++) {
                const int f4 = fb * 4 + c;
                float4 v = *(const float4*)&Kg[(size_t)(kt + row) * DH + f4 * 4];
                KtPt[(f4 * 4 + 0) * 64 + row] = v.x;
                KtPt[(f4 * 4 + 1) * 64 + row] = v.y;
                KtPt[(f4 * 4 + 2) * 64 + row] = v.z;
                KtPt[(f4 * 4 + 3) * 64 + row] = v.w;
            }
#pragma unroll
            for (int c = 0; c < 4; c++) {
                const int idx  = t + 256 * c;
                const int vrow = idx >> 4;
                const int vf4  = idx & 15;
                *(float4*)&Vs[vrow][vf4 * 4] =
                    *(const float4*)&Vg[(size_t)(kt + vrow) * DH + vf4 * 4];
            }
        }
        __syncthreads();

        float sc[4][4];
#pragma unroll
        for (int i = 0; i < 4; i++)
#pragma unroll
            for (int j = 0; j < 4; j++) sc[i][j] = 0.0f;

#pragma unroll 8
        for (int d = 0; d < DH; d++) {
            float4 qa = *(const float4*)&Qt[d][ty * 4];
            float4 ka = *(const float4*)&KtPt[d * 64 + tx * 4];
            float qv[4] = {qa.x, qa.y, qa.z, qa.w};
            float kv[4] = {ka.x, ka.y, ka.z, ka.w};
#pragma unroll
            for (int i = 0; i < 4; i++)
#pragma unroll
                for (int j = 0; j < 4; j++)
                    sc[i][j] = fmaf(qv[i], kv[j], sc[i][j]);
        }

        float mnew[4];
#pragma unroll
        for (int i = 0; i < 4; i++) {
            const int qg = q0 + ty * 4 + i;
            float4 mk = *(const float4*)&mask[((size_t)b * SEQ + qg) * SEQ + kt + tx * 4];
            sc[i][0] = fmaf(sc[i][0], scl, mk.x);
            sc[i][1] = fmaf(sc[i][1], scl, mk.y);
            sc[i][2] = fmaf(sc[i][2], scl, mk.z);
            sc[i][3] = fmaf(sc[i][3], scl, mk.w);
            float mx = fmaxf(fmaxf(sc[i][0], sc[i][1]), fmaxf(sc[i][2], sc[i][3]));
#pragma unroll
            for (int off = 8; off > 0; off >>= 1)
                mx = fmaxf(mx, __shfl_xor_sync(0xffffffffu, mx, off));
            mnew[i] = fmaxf(m_i[i], mx);
        }
        __syncthreads();

#pragma unroll
        for (int i = 0; i < 4; i++) {
            const float corr = __expf(m_i[i] - mnew[i]);
            float p0 = __expf(sc[i][0] - mnew[i]);
            float p1 = __expf(sc[i][1] - mnew[i]);
            float p2 = __expf(sc[i][2] - mnew[i]);
            float p3 = __expf(sc[i][3] - mnew[i]);
            *(float4*)&KtPt[(ty * 4 + i) * 64 + tx * 4] = make_float4(p0, p1, p2, p3);
            float rs = p0 + p1 + p2 + p3;
#pragma unroll
            for (int off = 8; off > 0; off >>= 1)
                rs += __shfl_xor_sync(0xffffffffu, rs, off);
            l_i[i] = l_i[i] * corr + rs;
            m_i[i] = mnew[i];
#pragma unroll
            for (int j = 0; j < 4; j++) o[i][j] *= corr;
        }
        __syncthreads();

#pragma unroll 4
        for (int k = 0; k < 64; k += 4) {
            float pv[4][4], vv[4][4];
#pragma unroll
            for (int i = 0; i < 4; i++)
                *(float4*)pv[i] = *(const float4*)&KtPt[(ty * 4 + i) * 64 + k];
#pragma unroll
            for (int kk = 0; kk < 4; kk++)
                *(float4*)vv[kk] = *(const float4*)&Vs[k + kk][tx * 4];
#pragma unroll
            for (int i = 0; i < 4; i++)
#pragma unroll
                for (int kk = 0; kk < 4; kk++)
#pragma unroll
                    for (int j = 0; j < 4; j++)
                        o[i][j] = fmaf(pv[i][kk], vv[kk][j], o[i][j]);
        }
        __syncthreads();
    }

#pragma unroll
    for (int i = 0; i < 4; i++) {
        const int qg = q0 + ty * 4 + i;
        const float inv = 1.0f / l_i[i];
        float4 v = make_float4(o[i][0] * inv, o[i][1] * inv,
                               o[i][2] * inv, o[i][3] * inv);
        *(float4*)&g_attn[((size_t)b * SEQ + qg) * DMODEL + h * DH + tx * 4] = v;
    }
}

// ---------------------------------------------------------------------------
extern "C" void kernel_launch(void* const* d_in, const int* in_sizes, int n_in,
                              void* d_out, int out_size)
{
    const float* x    = (const float*)d_in[0];
    const float* mask = (const float*)d_in[1];
    const float* wqkv = (const float*)d_in[2];
    const float* wout = (const float*)d_in[3];
    const float* bout = (const float*)d_in[4];
    float* out = (float*)d_out;

    (void)in_sizes; (void)n_in; (void)out_size;

    static bool attr_done = false;
    if (!attr_done) {
        cudaFuncSetAttribute(mma_gemm<0>, cudaFuncAttributeMaxDynamicSharedMemorySize, GEMM_SMEM);
        cudaFuncSetAttribute(mma_gemm<1>, cudaFuncAttributeMaxDynamicSharedMemorySize, GEMM_SMEM);
        attr_done = true;
    }

    // 1) QKV projection (tf32 mma.sync), scattered head-major
    mma_gemm<0><<<dim3((3 * DMODEL) / 128, (BATCH * SEQ) / 128), 256, GEMM_SMEM>>>(
        x, wqkv, nullptr, nullptr, BATCH * SEQ, 3 * DMODEL, DMODEL);

    // 2) flash attention (fp32)
    flash_kernel<<<dim3(SEQ / 64, BATCH * NH), 256>>>(mask);

    // 3) output projection + bias (tf32 mma.sync)
    mma_gemm<1><<<dim3(DMODEL / 128, (BATCH * SEQ) / 128), 256, GEMM_SMEM>>>(
        nullptr, wout, bout, out, BATCH * SEQ, DMODEL, DMODEL);
}

// round 13
// speedup vs baseline: 1.8902x; 1.4001x over previous
#include <cuda_runtime.h>
#include <cstdint>
#include <math.h>
#include <stddef.h>

#define NH     20
#define DH     64
#define DMODEL 1280
#define SEQ    2048
#define BATCH  2

// Scratch (no allocation allowed -> __device__ globals)
__device__ float g_Q[BATCH * NH * SEQ * DH];
__device__ float g_K[BATCH * NH * SEQ * DH];
__device__ float g_V[BATCH * NH * SEQ * DH];
__device__ float g_attn[BATCH * SEQ * DMODEL];

// ---------------------------------------------------------------------------
__device__ __forceinline__ float to_tf32(float x) {
    uint32_t u = __float_as_uint(x), r;
    asm("cvt.rna.tf32.f32 %0, %1;" : "=r"(r) : "r"(u));
    return __uint_as_float(r);
}
__device__ __forceinline__ uint32_t tf32_bits(float x) {
    uint32_t u = __float_as_uint(x), r;
    asm("cvt.rna.tf32.f32 %0, %1;" : "=r"(r) : "r"(u));
    return r;
}

// D += A*B, m16n8k8 tf32 (A row-major, B col-major fragments)
__device__ __forceinline__ void mma_tf32(float* c, const uint32_t* a, const uint32_t* b) {
    asm volatile(
        "mma.sync.aligned.m16n8k8.row.col.f32.tf32.tf32.f32 "
        "{%0,%1,%2,%3}, {%4,%5,%6,%7}, {%8,%9}, {%0,%1,%2,%3};"
        : "+f"(c[0]), "+f"(c[1]), "+f"(c[2]), "+f"(c[3])
        : "r"(a[0]), "r"(a[1]), "r"(a[2]), "r"(a[3]), "r"(b[0]), "r"(b[1]));
}

// ---------------------------------------------------------------------------
// tf32 mma.sync GEMM: C[M,N] = A[M,K] @ B[K,N]  (unchanged from R8, proven)
// ---------------------------------------------------------------------------
#define ASTR 36
#define BSTR 132
#define A_FLOATS (128 * ASTR)
#define B_FLOATS (32 * BSTR)
#define GEMM_SMEM ((2 * A_FLOATS + 2 * B_FLOATS) * 4)

template <int MODE>
__global__ __launch_bounds__(256)
void mma_gemm(const float* __restrict__ A, const float* __restrict__ B,
              const float* __restrict__ bias, float* __restrict__ C,
              int M, int N, int K)
{
    extern __shared__ float sm[];
    float* As[2] = { sm, sm + A_FLOATS };
    float* Bs[2] = { sm + 2 * A_FLOATS, sm + 2 * A_FLOATS + B_FLOATS };

    const int t    = threadIdx.x;
    const int lane = t & 31;
    const int wid  = t >> 5;
    const int g4   = lane >> 2;
    const int t4   = lane & 3;
    const int m0   = blockIdx.y * 128;
    const int n0   = blockIdx.x * 128;
    const int wm   = (wid & 3) * 32;
    const int wn   = (wid >> 2) * 64;

    const float* Ap = (MODE == 1) ? g_attn : A;

    const int am  = t >> 3;
    const int ak4 = t & 7;
    const int bk  = t >> 3;
    const int bn4 = t & 7;

    float cacc[2][8][4];
#pragma unroll
    for (int i = 0; i < 2; i++)
#pragma unroll
        for (int j = 0; j < 8; j++)
#pragma unroll
            for (int q = 0; q < 4; q++) cacc[i][j][q] = 0.0f;

    const int nk = K >> 5;

    {
        float4 ra[4], rb[4];
#pragma unroll
        for (int c = 0; c < 4; c++) {
            ra[c] = *(const float4*)&Ap[(size_t)(m0 + c * 32 + am) * K + ak4 * 4];
            rb[c] = *(const float4*)&B[(size_t)bk * N + n0 + (bn4 + 8 * c) * 4];
        }
#pragma unroll
        for (int c = 0; c < 4; c++) {
            float4 va = ra[c], vb = rb[c];
            va.x = to_tf32(va.x); va.y = to_tf32(va.y); va.z = to_tf32(va.z); va.w = to_tf32(va.w);
            vb.x = to_tf32(vb.x); vb.y = to_tf32(vb.y); vb.z = to_tf32(vb.z); vb.w = to_tf32(vb.w);
            *(float4*)&As[0][(c * 32 + am) * ASTR + ak4 * 4] = va;
            *(float4*)&Bs[0][bk * BSTR + (bn4 + 8 * c) * 4] = vb;
        }
    }
    __syncthreads();

    for (int kt = 0; kt < nk; kt++) {
        const int cur = kt & 1;
        float4 ra[4], rb[4];
        if (kt + 1 < nk) {
            const int k0 = (kt + 1) * 32;
#pragma unroll
            for (int c = 0; c < 4; c++) {
                ra[c] = *(const float4*)&Ap[(size_t)(m0 + c * 32 + am) * K + k0 + ak4 * 4];
                rb[c] = *(const float4*)&B[(size_t)(k0 + bk) * N + n0 + (bn4 + 8 * c) * 4];
            }
        }

        const float* Ab = As[cur];
        const float* Bb = Bs[cur];
#pragma unroll
        for (int ks = 0; ks < 4; ks++) {
            const int kk = ks * 8 + t4;
            uint32_t af[2][4], bf[8][2];
#pragma unroll
            for (int mt = 0; mt < 2; mt++) {
                const int r0 = wm + mt * 16 + g4;
                af[mt][0] = __float_as_uint(Ab[r0 * ASTR + kk]);
                af[mt][1] = __float_as_uint(Ab[(r0 + 8) * ASTR + kk]);
                af[mt][2] = __float_as_uint(Ab[r0 * ASTR + kk + 4]);
                af[mt][3] = __float_as_uint(Ab[(r0 + 8) * ASTR + kk + 4]);
            }
#pragma unroll
            for (int nt = 0; nt < 8; nt++) {
                const int nn = wn + nt * 8 + g4;
                bf[nt][0] = __float_as_uint(Bb[kk * BSTR + nn]);
                bf[nt][1] = __float_as_uint(Bb[(kk + 4) * BSTR + nn]);
            }
#pragma unroll
            for (int mt = 0; mt < 2; mt++)
#pragma unroll
                for (int nt = 0; nt < 8; nt++)
                    mma_tf32(cacc[mt][nt], af[mt], bf[nt]);
        }

        if (kt + 1 < nk) {
            const int nxt = (kt + 1) & 1;
#pragma unroll
            for (int c = 0; c < 4; c++) {
                float4 va = ra[c], vb = rb[c];
                va.x = to_tf32(va.x); va.y = to_tf32(va.y); va.z = to_tf32(va.z); va.w = to_tf32(va.w);
                vb.x = to_tf32(vb.x); vb.y = to_tf32(vb.y); vb.z = to_tf32(vb.z); vb.w = to_tf32(vb.w);
                *(float4*)&As[nxt][(c * 32 + am) * ASTR + ak4 * 4] = va;
                *(float4*)&Bs[nxt][bk * BSTR + (bn4 + 8 * c) * 4] = vb;
            }
        }
        __syncthreads();
    }

#pragma unroll
    for (int mt = 0; mt < 2; mt++) {
#pragma unroll
        for (int half = 0; half < 2; half++) {
            const int r = m0 + wm + mt * 16 + g4 + half * 8;
#pragma unroll
            for (int nt = 0; nt < 8; nt++) {
                const float v0 = cacc[mt][nt][half * 2 + 0];
                const float v1 = cacc[mt][nt][half * 2 + 1];
                const int ncol = wn + nt * 8 + t4 * 2;
                if (MODE == 0) {
                    const int gn   = n0 + ncol;
                    const int part = gn / DMODEL;
                    const int rem  = gn - part * DMODEL;
                    float* base = (part == 0) ? g_Q : (part == 1) ? g_K : g_V;
                    const int h = rem >> 6, d = rem & 63;
                    const int b = r >> 11, s = r & 2047;
                    *(float2*)&base[(((size_t)(b * NH + h)) * SEQ + s) * DH + d] =
                        make_float2(v0, v1);
                } else {
                    const int gn = n0 + ncol;
                    *(float2*)&C[(size_t)r * N + gn] =
                        make_float2(v0 + bias[gn], v1 + bias[gn + 1]);
                }
            }
        }
    }
}

// ---------------------------------------------------------------------------
// Tensor-core flash attention (tf32 mma.sync), online softmax.
// Grid: (SEQ/64, BATCH*NH), 128 threads = 4 warps; warp owns 16 q-rows.
// K-tile = 64 tokens. Kt[d][tok] stride 72 (QK^T B-frag LDS conflict-free),
// Vt[d][tok] stride 68 (PV B-frag LDS conflict-free).
// P stays in registers: C-frag -> A-frag via quad shuffle permute.
// ---------------------------------------------------------------------------
#define KSTR 72
#define VSTR 68

__global__ __launch_bounds__(128)
void flash_mma(const float* __restrict__ mask)
{
    __shared__ float Kt[DH * KSTR];   // [d][tok]
    __shared__ float Vt[DH * VSTR];   // [d][tok]

    const int t    = threadIdx.x;
    const int lane = t & 31;
    const int w    = t >> 5;
    const int g4   = lane >> 2;
    const int t4   = lane & 3;
    const int q0   = blockIdx.x * 64;
    const int bh   = blockIdx.y;
    const int b    = bh / NH;
    const int h    = bh % NH;

    const float* Qg = g_Q + (size_t)bh * SEQ * DH;
    const float* Kg = g_K + (size_t)bh * SEQ * DH;
    const float* Vg = g_V + (size_t)bh * SEQ * DH;

    // Q A-fragments, pre-scaled by 1/sqrt(64), tf32-rounded, resident all kernel
    uint32_t aq[8][4];
    {
        const int r0 = q0 + w * 16 + g4;
#pragma unroll
        for (int kd = 0; kd < 8; kd++) {
            aq[kd][0] = tf32_bits(Qg[(size_t)r0 * DH + kd * 8 + t4] * 0.125f);
            aq[kd][1] = tf32_bits(Qg[(size_t)(r0 + 8) * DH + kd * 8 + t4] * 0.125f);
            aq[kd][2] = tf32_bits(Qg[(size_t)r0 * DH + kd * 8 + t4 + 4] * 0.125f);
            aq[kd][3] = tf32_bits(Qg[(size_t)(r0 + 8) * DH + kd * 8 + t4 + 4] * 0.125f);
        }
    }

    float m0r = -1e30f, m1r = -1e30f, l0 = 0.0f, l1 = 0.0f;
    float co[8][4];
#pragma unroll
    for (int nt = 0; nt < 8; nt++)
#pragma unroll
        for (int j = 0; j < 4; j++) co[nt][j] = 0.0f;

    const float* m0p = mask + ((size_t)b * SEQ + (q0 + w * 16 + g4)) * SEQ;
    const float* m1p = m0p + 8 * SEQ;

    for (int kt = 0; kt < SEQ; kt += 64) {
        // ---- load K,V tiles transposed [d][tok], tf32-rounded ----
        {
            const int row = t & 63;
            const int fb  = t >> 6;           // 0 or 1
#pragma unroll
            for (int c = 0; c < 8; c++) {
                const int f4 = fb * 8 + c;    // 0..15
                float4 kv = *(const float4*)&Kg[(size_t)(kt + row) * DH + f4 * 4];
                Kt[(f4 * 4 + 0) * KSTR + row] = to_tf32(kv.x);
                Kt[(f4 * 4 + 1) * KSTR + row] = to_tf32(kv.y);
                Kt[(f4 * 4 + 2) * KSTR + row] = to_tf32(kv.z);
                Kt[(f4 * 4 + 3) * KSTR + row] = to_tf32(kv.w);
                float4 vv = *(const float4*)&Vg[(size_t)(kt + row) * DH + f4 * 4];
                Vt[(f4 * 4 + 0) * VSTR + row] = to_tf32(vv.x);
                Vt[(f4 * 4 + 1) * VSTR + row] = to_tf32(vv.y);
                Vt[(f4 * 4 + 2) * VSTR + row] = to_tf32(vv.z);
                Vt[(f4 * 4 + 3) * VSTR + row] = to_tf32(vv.w);
            }
        }
        __syncthreads();

        // ---- QK^T: cs[nt] = 16x8 score tiles over 64 tokens ----
        float cs[8][4];
#pragma unroll
        for (int nt = 0; nt < 8; nt++)
#pragma unroll
            for (int j = 0; j < 4; j++) cs[nt][j] = 0.0f;

#pragma unroll
        for (int ks = 0; ks < 8; ks++) {
#pragma unroll
            for (int nt = 0; nt < 8; nt++) {
                uint32_t bf[2];
                bf[0] = __float_as_uint(Kt[(ks * 8 + t4) * KSTR + nt * 8 + g4]);
                bf[1] = __float_as_uint(Kt[(ks * 8 + t4 + 4) * KSTR + nt * 8 + g4]);
                mma_tf32(cs[nt], aq[ks], bf);
            }
        }

        // ---- mask add + row max (quad shuffle reduce) ----
        float mx0 = -1e30f, mx1 = -1e30f;
#pragma unroll
        for (int nt = 0; nt < 8; nt++) {
            float2 k0 = *(const float2*)&m0p[kt + nt * 8 + t4 * 2];
            float2 k1 = *(const float2*)&m1p[kt + nt * 8 + t4 * 2];
            cs[nt][0] += k0.x; cs[nt][1] += k0.y;
            cs[nt][2] += k1.x; cs[nt][3] += k1.y;
            mx0 = fmaxf(mx0, fmaxf(cs[nt][0], cs[nt][1]));
            mx1 = fmaxf(mx1, fmaxf(cs[nt][2], cs[nt][3]));
        }
        mx0 = fmaxf(mx0, __shfl_xor_sync(0xffffffffu, mx0, 1));
        mx0 = fmaxf(mx0, __shfl_xor_sync(0xffffffffu, mx0, 2));
        mx1 = fmaxf(mx1, __shfl_xor_sync(0xffffffffu, mx1, 1));
        mx1 = fmaxf(mx1, __shfl_xor_sync(0xffffffffu, mx1, 2));

        const float mn0 = fmaxf(m0r, mx0), mn1 = fmaxf(m1r, mx1);
        const float corr0 = __expf(m0r - mn0), corr1 = __expf(m1r - mn1);
        m0r = mn0; m1r = mn1;

        // ---- exp (tf32-rounded) + row sum ----
        float rs0 = 0.0f, rs1 = 0.0f;
#pragma unroll
        for (int nt = 0; nt < 8; nt++) {
            cs[nt][0] = to_tf32(__expf(cs[nt][0] - mn0));
            cs[nt][1] = to_tf32(__expf(cs[nt][1] - mn0));
            cs[nt][2] = to_tf32(__expf(cs[nt][2] - mn1));
            cs[nt][3] = to_tf32(__expf(cs[nt][3] - mn1));
            rs0 += cs[nt][0] + cs[nt][1];
            rs1 += cs[nt][2] + cs[nt][3];
        }
        rs0 += __shfl_xor_sync(0xffffffffu, rs0, 1);
        rs0 += __shfl_xor_sync(0xffffffffu, rs0, 2);
        rs1 += __shfl_xor_sync(0xffffffffu, rs1, 1);
        rs1 += __shfl_xor_sync(0xffffffffu, rs1, 2);
        l0 = l0 * corr0 + rs0;
        l1 = l1 * corr1 + rs1;
#pragma unroll
        for (int nt = 0; nt < 8; nt++) {
            co[nt][0] *= corr0; co[nt][1] *= corr0;
            co[nt][2] *= corr1; co[nt][3] *= corr1;
        }

        // ---- PV: permute P C-frags -> A-frags (quad shuffles), mma with V ----
        const int srcA = (lane & ~3) | (t4 >> 1);
        const int srcB = srcA + 2;
        const bool odd = (t4 & 1) != 0;
#pragma unroll
        for (int ks = 0; ks < 8; ks++) {
            uint32_t ap[4];
            {
                float s0 = __shfl_sync(0xffffffffu, cs[ks][0], srcA);
                float s1 = __shfl_sync(0xffffffffu, cs[ks][1], srcA);
                float s2 = __shfl_sync(0xffffffffu, cs[ks][0], srcB);
                float s3 = __shfl_sync(0xffffffffu, cs[ks][1], srcB);
                ap[0] = __float_as_uint(odd ? s1 : s0);
                ap[2] = __float_as_uint(odd ? s3 : s2);
                float u0 = __shfl_sync(0xffffffffu, cs[ks][2], srcA);
                float u1 = __shfl_sync(0xffffffffu, cs[ks][3], srcA);
                float u2 = __shfl_sync(0xffffffffu, cs[ks][2], srcB);
                float u3 = __shfl_sync(0xffffffffu, cs[ks][3], srcB);
                ap[1] = __float_as_uint(odd ? u1 : u0);
                ap[3] = __float_as_uint(odd ? u3 : u2);
            }
#pragma unroll
            for (int nt = 0; nt < 8; nt++) {
                uint32_t bv[2];
                bv[0] = __float_as_uint(Vt[(nt * 8 + g4) * VSTR + ks * 8 + t4]);
                bv[1] = __float_as_uint(Vt[(nt * 8 + g4) * VSTR + ks * 8 + t4 + 4]);
                mma_tf32(co[nt], ap, bv);
            }
        }
        __syncthreads();   // all warps done with Kt/Vt before next tile load
    }

    // ---- normalize, write attn in [b][s][h*64+d] layout ----
    const float inv0 = 1.0f / l0, inv1 = 1.0f / l1;
    const int r0 = q0 + w * 16 + g4;
    float* op0 = g_attn + ((size_t)b * SEQ + r0) * DMODEL + h * DH;
    float* op1 = op0 + 8 * DMODEL;
#pragma unroll
    for (int nt = 0; nt < 8; nt++) {
        *(float2*)&op0[nt * 8 + t4 * 2] = make_float2(co[nt][0] * inv0, co[nt][1] * inv0);
        *(float2*)&op1[nt * 8 + t4 * 2] = make_float2(co[nt][2] * inv1, co[nt][3] * inv1);
    }
}

// ---------------------------------------------------------------------------
extern "C" void kernel_launch(void* const* d_in, const int* in_sizes, int n_in,
                              void* d_out, int out_size)
{
    const float* x    = (const float*)d_in[0];
    const float* mask = (const float*)d_in[1];
    const float* wqkv = (const float*)d_in[2];
    const float* wout = (const float*)d_in[3];
    const float* bout = (const float*)d_in[4];
    float* out = (float*)d_out;

    (void)in_sizes; (void)n_in; (void)out_size;

    static bool attr_done = false;
    if (!attr_done) {
        cudaFuncSetAttribute(mma_gemm<0>, cudaFuncAttributeMaxDynamicSharedMemorySize, GEMM_SMEM);
        cudaFuncSetAttribute(mma_gemm<1>, cudaFuncAttributeMaxDynamicSharedMemorySize, GEMM_SMEM);
        attr_done = true;
    }

    // 1) QKV projection (tf32 mma.sync), scattered head-major
    mma_gemm<0><<<dim3((3 * DMODEL) / 128, (BATCH * SEQ) / 128), 256, GEMM_SMEM>>>(
        x, wqkv, nullptr, nullptr, BATCH * SEQ, 3 * DMODEL, DMODEL);

    // 2) flash attention (tf32 mma.sync)
    flash_mma<<<dim3(SEQ / 64, BATCH * NH), 128>>>(mask);

    // 3) output projection + bias (tf32 mma.sync)
    mma_gemm<1><<<dim3(DMODEL / 128, (BATCH * SEQ) / 128), 256, GEMM_SMEM>>>(
        nullptr, wout, bout, out, BATCH * SEQ, DMODEL, DMODEL);
}

// round 16
// speedup vs baseline: 3.1889x; 1.6870x over previous
#include <cuda_runtime.h>
#include <cstdint>
#include <math.h>
#include <stddef.h>

#define NH     20
#define DH     64
#define DMODEL 1280
#define SEQ    2048
#define BATCH  2

// Scratch (no allocation allowed -> __device__ globals)
__device__ float g_Q[BATCH * NH * SEQ * DH];
__device__ float g_K[BATCH * NH * SEQ * DH];
__device__ float g_V[BATCH * NH * SEQ * DH];
__device__ float g_attn[BATCH * SEQ * DMODEL];

// ---------------------------------------------------------------------------
__device__ __forceinline__ uint32_t smem_u32(const void* p) {
    return (uint32_t)__cvta_generic_to_shared(p);
}
__device__ __forceinline__ float to_tf32(float x) {
    uint32_t u = __float_as_uint(x), r;
    asm("cvt.rna.tf32.f32 %0, %1;" : "=r"(r) : "r"(u));
    return __uint_as_float(r);
}
__device__ __forceinline__ uint32_t tf32_bits(float x) {
    uint32_t u = __float_as_uint(x), r;
    asm("cvt.rna.tf32.f32 %0, %1;" : "=r"(r) : "r"(u));
    return r;
}
__device__ __forceinline__ void cp_async16(uint32_t dst, const void* src) {
    asm volatile("cp.async.cg.shared.global [%0], [%1], 16;" :: "r"(dst), "l"(src));
}
#define CP_COMMIT() asm volatile("cp.async.commit_group;" ::: "memory")
#define CP_WAIT(n)  asm volatile("cp.async.wait_group %0;" :: "n"(n) : "memory")

// D += A*B, m16n8k8 tf32 (A row-major, B col-major fragments)
__device__ __forceinline__ void mma_tf32(float* c, const uint32_t* a, const uint32_t* b) {
    asm volatile(
        "mma.sync.aligned.m16n8k8.row.col.f32.tf32.tf32.f32 "
        "{%0,%1,%2,%3}, {%4,%5,%6,%7}, {%8,%9}, {%0,%1,%2,%3};"
        : "+f"(c[0]), "+f"(c[1]), "+f"(c[2]), "+f"(c[3])
        : "r"(a[0]), "r"(a[1]), "r"(a[2]), "r"(a[3]), "r"(b[0]), "r"(b[1]));
}

// ---------------------------------------------------------------------------
// tf32 mma.sync GEMM with cp.async 2-stage pipeline.
// CTA 128x128, BK=32, 8 warps (warp tile 32x64), 2 CTAs/SM.
// smem holds raw fp32; cvt.rna applied at fragment-load time.
// MODE 0: A = hidden states; epilogue scatters QKV head-major.
// MODE 1: A = g_attn; epilogue adds bias, stores C.
// ---------------------------------------------------------------------------
#define ASTR 36     // bank: 4*g4 + t4 (+8ks)  -> injective
#define BSTR 136    // bank: 8*t4 + g4 (+8nt)  -> injective (132 had 2-way conflicts)
#define A_FLOATS (128 * ASTR)            // 4608
#define B_FLOATS (32 * BSTR)             // 4352
#define STAGE_FLOATS (A_FLOATS + B_FLOATS)
#define GEMM_SMEM (2 * STAGE_FLOATS * 4) // 71680 B

template <int MODE>
__global__ __launch_bounds__(256, 2)
void mma_gemm(const float* __restrict__ A, const float* __restrict__ B,
              const float* __restrict__ bias, float* __restrict__ C,
              int M, int N, int K)
{
    extern __shared__ float sm[];

    const int t    = threadIdx.x;
    const int lane = t & 31;
    const int wid  = t >> 5;
    const int g4   = lane >> 2;
    const int t4   = lane & 3;
    const int m0   = blockIdx.y * 128;
    const int n0   = blockIdx.x * 128;
    const int wm   = (wid & 3) * 32;
    const int wn   = (wid >> 2) * 64;

    const float* Ap = (MODE == 1) ? g_attn : A;

    // cp.async assignments
    const int ar0 = t >> 3;       // A row base (0..31), rows ar0 + 32c
    const int ac  = t & 7;        // A 16B-chunk in k
    const int br0 = t >> 5;       // B k-row base (0..7), rows br0 + 8c
    const int bc  = t & 31;       // B 16B-chunk in n

    const float* a_src = Ap + (size_t)(m0 + ar0) * K + ac * 4;
    const float* b_src = B + (size_t)br0 * N + n0 + bc * 4;
    const uint32_t a_dst = smem_u32(sm) + (ar0 * ASTR + ac * 4) * 4;
    const uint32_t b_dst = smem_u32(sm) + (A_FLOATS + br0 * BSTR + bc * 4) * 4;
    const uint32_t stage_b = STAGE_FLOATS * 4;

    float cacc[2][8][4];
#pragma unroll
    for (int i = 0; i < 2; i++)
#pragma unroll
        for (int j = 0; j < 8; j++)
#pragma unroll
            for (int q = 0; q < 4; q++) cacc[i][j][q] = 0.0f;

    const int nk = K >> 5;

    // prologue: stage 0
    {
#pragma unroll
        for (int c = 0; c < 4; c++)
            cp_async16(a_dst + c * 32 * ASTR * 4, a_src + (size_t)(32 * c) * K);
#pragma unroll
        for (int c = 0; c < 4; c++)
            cp_async16(b_dst + c * 8 * BSTR * 4, b_src + (size_t)(8 * c) * N);
        CP_COMMIT();
    }

    for (int kt = 0; kt < nk; kt++) {
        if (kt + 1 < nk) {
            const uint32_t sb = ((kt + 1) & 1) * stage_b;
            const float* as = a_src + (size_t)(kt + 1) * 32;
            const float* bs = b_src + (size_t)(kt + 1) * 32 * N;
#pragma unroll
            for (int c = 0; c < 4; c++)
                cp_async16(a_dst + sb + c * 32 * ASTR * 4, as + (size_t)(32 * c) * K);
#pragma unroll
            for (int c = 0; c < 4; c++)
                cp_async16(b_dst + sb + c * 8 * BSTR * 4, bs + (size_t)(8 * c) * N);
            CP_COMMIT();
            CP_WAIT(1);
        } else {
            CP_WAIT(0);
        }
        __syncthreads();

        const float* Ab = sm + (kt & 1) * STAGE_FLOATS;
        const float* Bb = Ab + A_FLOATS;
#pragma unroll
        for (int ks = 0; ks < 4; ks++) {
            const int kk = ks * 8 + t4;
            uint32_t af[2][4], bf[8][2];
#pragma unroll
            for (int mt = 0; mt < 2; mt++) {
                const int r0 = wm + mt * 16 + g4;
                af[mt][0] = tf32_bits(Ab[r0 * ASTR + kk]);
                af[mt][1] = tf32_bits(Ab[(r0 + 8) * ASTR + kk]);
                af[mt][2] = tf32_bits(Ab[r0 * ASTR + kk + 4]);
                af[mt][3] = tf32_bits(Ab[(r0 + 8) * ASTR + kk + 4]);
            }
#pragma unroll
            for (int nt = 0; nt < 8; nt++) {
                const int nn = wn + nt * 8 + g4;
                bf[nt][0] = tf32_bits(Bb[kk * BSTR + nn]);
                bf[nt][1] = tf32_bits(Bb[(kk + 4) * BSTR + nn]);
            }
#pragma unroll
            for (int mt = 0; mt < 2; mt++)
#pragma unroll
                for (int nt = 0; nt < 8; nt++)
                    mma_tf32(cacc[mt][nt], af[mt], bf[nt]);
        }
        __syncthreads();
    }

    // ---- epilogue ----
#pragma unroll
    for (int mt = 0; mt < 2; mt++) {
#pragma unroll
        for (int half = 0; half < 2; half++) {
            const int r = m0 + wm + mt * 16 + g4 + half * 8;
#pragma unroll
            for (int nt = 0; nt < 8; nt++) {
                const float v0 = cacc[mt][nt][half * 2 + 0];
                const float v1 = cacc[mt][nt][half * 2 + 1];
                const int ncol = wn + nt * 8 + t4 * 2;
                if (MODE == 0) {
                    const int gn   = n0 + ncol;
                    const int part = gn / DMODEL;
                    const int rem  = gn - part * DMODEL;
                    float* base = (part == 0) ? g_Q : (part == 1) ? g_K : g_V;
                    const int h = rem >> 6, d = rem & 63;
                    const int b = r >> 11, s = r & 2047;
                    *(float2*)&base[(((size_t)(b * NH + h)) * SEQ + s) * DH + d] =
                        make_float2(v0, v1);
                } else {
                    const int gn = n0 + ncol;
                    *(float2*)&C[(size_t)r * N + gn] =
                        make_float2(v0 + bias[gn], v1 + bias[gn + 1]);
                }
            }
        }
    }
}

// ---------------------------------------------------------------------------
// Tensor-core flash attention, cp.async double-buffered K/V tiles.
// Grid: (SEQ/64, BATCH*NH), 128 threads = 4 warps; warp owns 16 q-rows.
// K/V in natural [tok][d] layout, raw fp32; pads 68/72 make both QK^T and PV
// B-fragment scalar LDS bank-injective. cvt.rna at fragment load.
// P stays in registers (quad-shuffle C-frag -> A-frag permute).
// ---------------------------------------------------------------------------
#define FKSTR 68    // QK bank: 4*g4 + t4 -> injective
#define FVSTR 72    // PV bank: 8*t4 + g4 -> injective
#define FK_FLOATS (64 * FKSTR)            // 4352
#define FV_FLOATS (64 * FVSTR)            // 4608
#define FSTAGE (FK_FLOATS + FV_FLOATS)    // 8960
#define FLASH_SMEM (2 * FSTAGE * 4)       // 71680 B

__global__ __launch_bounds__(128, 3)
void flash_mma(const float* __restrict__ mask)
{
    extern __shared__ float smf[];

    const int t    = threadIdx.x;
    const int lane = t & 31;
    const int w    = t >> 5;
    const int g4   = lane >> 2;
    const int t4   = lane & 3;
    const int q0   = blockIdx.x * 64;
    const int bh   = blockIdx.y;
    const int b    = bh / NH;
    const int h    = bh % NH;

    const float* Qg = g_Q + (size_t)bh * SEQ * DH;
    const float* Kg = g_K + (size_t)bh * SEQ * DH;
    const float* Vg = g_V + (size_t)bh * SEQ * DH;

    // cp.async assignments: 64 tok x 16 chunks per matrix, 128 threads -> 8 each
    const int ftok = t >> 4;        // token base (0..7), tokens ftok + 8c
    const int fch  = t & 15;        // 16B chunk in d
    const float* k_src = Kg + (size_t)ftok * DH + fch * 4;
    const float* v_src = Vg + (size_t)ftok * DH + fch * 4;
    const uint32_t k_dst = smem_u32(smf) + (ftok * FKSTR + fch * 4) * 4;
    const uint32_t v_dst = smem_u32(smf) + (FK_FLOATS + ftok * FVSTR + fch * 4) * 4;
    const uint32_t fstage_b = FSTAGE * 4;

    // Q A-fragments, pre-scaled by 1/sqrt(64), tf32-rounded, resident all kernel
    uint32_t aq[8][4];
    {
        const int r0 = q0 + w * 16 + g4;
#pragma unroll
        for (int kd = 0; kd < 8; kd++) {
            aq[kd][0] = tf32_bits(Qg[(size_t)r0 * DH + kd * 8 + t4] * 0.125f);
            aq[kd][1] = tf32_bits(Qg[(size_t)(r0 + 8) * DH + kd * 8 + t4] * 0.125f);
            aq[kd][2] = tf32_bits(Qg[(size_t)r0 * DH + kd * 8 + t4 + 4] * 0.125f);
            aq[kd][3] = tf32_bits(Qg[(size_t)(r0 + 8) * DH + kd * 8 + t4 + 4] * 0.125f);
        }
    }

    float m0r = -1e30f, m1r = -1e30f, l0 = 0.0f, l1 = 0.0f;
    float co[8][4];
#pragma unroll
    for (int nt = 0; nt < 8; nt++)
#pragma unroll
        for (int j = 0; j < 4; j++) co[nt][j] = 0.0f;

    const float* m0p = mask + ((size_t)b * SEQ + (q0 + w * 16 + g4)) * SEQ;
    const float* m1p = m0p + 8 * SEQ;

    // prologue: tile 0 into stage 0
    {
#pragma unroll
        for (int c = 0; c < 8; c++)
            cp_async16(k_dst + c * 8 * FKSTR * 4, k_src + (size_t)(8 * c) * DH);
#pragma unroll
        for (int c = 0; c < 8; c++)
            cp_async16(v_dst + c * 8 * FVSTR * 4, v_src + (size_t)(8 * c) * DH);
        CP_COMMIT();
    }

    for (int ti = 0; ti < SEQ / 64; ti++) {
        const int kt = ti * 64;

        // issue next tile
        if (ti + 1 < SEQ / 64) {
            const uint32_t sb = ((ti + 1) & 1) * fstage_b;
            const float* ks = k_src + (size_t)(ti + 1) * 64 * DH;
            const float* vs = v_src + (size_t)(ti + 1) * 64 * DH;
#pragma unroll
            for (int c = 0; c < 8; c++)
                cp_async16(k_dst + sb + c * 8 * FKSTR * 4, ks + (size_t)(8 * c) * DH);
#pragma unroll
            for (int c = 0; c < 8; c++)
                cp_async16(v_dst + sb + c * 8 * FVSTR * 4, vs + (size_t)(8 * c) * DH);
            CP_COMMIT();
        }

        // mask prefetch (LDG latency overlaps the cp.async wait + mma work)
        float2 mk0[8], mk1[8];
#pragma unroll
        for (int nt = 0; nt < 8; nt++) {
            mk0[nt] = *(const float2*)&m0p[kt + nt * 8 + t4 * 2];
            mk1[nt] = *(const float2*)&m1p[kt + nt * 8 + t4 * 2];
        }

        if (ti + 1 < SEQ / 64) { CP_WAIT(1); } else { CP_WAIT(0); }
        __syncthreads();

        const float* Kn = smf + (ti & 1) * FSTAGE;
        const float* Vn = Kn + FK_FLOATS;

        // ---- QK^T ----
        float cs[8][4];
#pragma unroll
        for (int nt = 0; nt < 8; nt++)
#pragma unroll
            for (int j = 0; j < 4; j++) cs[nt][j] = 0.0f;

#pragma unroll
        for (int ks = 0; ks < 8; ks++) {
#pragma unroll
            for (int nt = 0; nt < 8; nt++) {
                uint32_t bf[2];
                bf[0] = tf32_bits(Kn[(nt * 8 + g4) * FKSTR + ks * 8 + t4]);
                bf[1] = tf32_bits(Kn[(nt * 8 + g4) * FKSTR + ks * 8 + t4 + 4]);
                mma_tf32(cs[nt], aq[ks], bf);
            }
        }

        // ---- mask add + row max (quad shuffle reduce) ----
        float mx0 = -1e30f, mx1 = -1e30f;
#pragma unroll
        for (int nt = 0; nt < 8; nt++) {
            cs[nt][0] += mk0[nt].x; cs[nt][1] += mk0[nt].y;
            cs[nt][2] += mk1[nt].x; cs[nt][3] += mk1[nt].y;
            mx0 = fmaxf(mx0, fmaxf(cs[nt][0], cs[nt][1]));
            mx1 = fmaxf(mx1, fmaxf(cs[nt][2], cs[nt][3]));
        }
        mx0 = fmaxf(mx0, __shfl_xor_sync(0xffffffffu, mx0, 1));
        mx0 = fmaxf(mx0, __shfl_xor_sync(0xffffffffu, mx0, 2));
        mx1 = fmaxf(mx1, __shfl_xor_sync(0xffffffffu, mx1, 1));
        mx1 = fmaxf(mx1, __shfl_xor_sync(0xffffffffu, mx1, 2));

        const float mn0 = fmaxf(m0r, mx0), mn1 = fmaxf(m1r, mx1);
        const float corr0 = __expf(m0r - mn0), corr1 = __expf(m1r - mn1);
        m0r = mn0; m1r = mn1;

        // ---- exp (tf32-rounded) + row sum ----
        float rs0 = 0.0f, rs1 = 0.0f;
#pragma unroll
        for (int nt = 0; nt < 8; nt++) {
            cs[nt][0] = to_tf32(__expf(cs[nt][0] - mn0));
            cs[nt][1] = to_tf32(__expf(cs[nt][1] - mn0));
            cs[nt][2] = to_tf32(__expf(cs[nt][2] - mn1));
            cs[nt][3] = to_tf32(__expf(cs[nt][3] - mn1));
            rs0 += cs[nt][0] + cs[nt][1];
            rs1 += cs[nt][2] + cs[nt][3];
        }
        rs0 += __shfl_xor_sync(0xffffffffu, rs0, 1);
        rs0 += __shfl_xor_sync(0xffffffffu, rs0, 2);
        rs1 += __shfl_xor_sync(0xffffffffu, rs1, 1);
        rs1 += __shfl_xor_sync(0xffffffffu, rs1, 2);
        l0 = l0 * corr0 + rs0;
        l1 = l1 * corr1 + rs1;
#pragma unroll
        for (int nt = 0; nt < 8; nt++) {
            co[nt][0] *= corr0; co[nt][1] *= corr0;
            co[nt][2] *= corr1; co[nt][3] *= corr1;
        }

        // ---- PV: permute P C-frags -> A-frags (quad shuffles), mma with V ----
        const int srcA = (lane & ~3) | (t4 >> 1);
        const int srcB = srcA + 2;
        const bool odd = (t4 & 1) != 0;
#pragma unroll
        for (int ks = 0; ks < 8; ks++) {
            uint32_t ap[4];
            {
                float s0 = __shfl_sync(0xffffffffu, cs[ks][0], srcA);
                float s1 = __shfl_sync(0xffffffffu, cs[ks][1], srcA);
                float s2 = __shfl_sync(0xffffffffu, cs[ks][0], srcB);
                float s3 = __shfl_sync(0xffffffffu, cs[ks][1], srcB);
                ap[0] = __float_as_uint(odd ? s1 : s0);
                ap[2] = __float_as_uint(odd ? s3 : s2);
                float u0 = __shfl_sync(0xffffffffu, cs[ks][2], srcA);
                float u1 = __shfl_sync(0xffffffffu, cs[ks][3], srcA);
                float u2 = __shfl_sync(0xffffffffu, cs[ks][2], srcB);
                float u3 = __shfl_sync(0xffffffffu, cs[ks][3], srcB);
                ap[1] = __float_as_uint(odd ? u1 : u0);
                ap[3] = __float_as_uint(odd ? u3 : u2);
            }
#pragma unroll
            for (int nt = 0; nt < 8; nt++) {
                uint32_t bv[2];
                bv[0] = tf32_bits(Vn[(ks * 8 + t4) * FVSTR + nt * 8 + g4]);
                bv[1] = tf32_bits(Vn[(ks * 8 + t4 + 4) * FVSTR + nt * 8 + g4]);
                mma_tf32(co[nt], ap, bv);
            }
        }
        __syncthreads();   // all warps done with Kn/Vn before stage reuse
    }

    // ---- normalize, write attn in [b][s][h*64+d] layout ----
    const float inv0 = 1.0f / l0, inv1 = 1.0f / l1;
    const int r0 = q0 + w * 16 + g4;
    float* op0 = g_attn + ((size_t)b * SEQ + r0) * DMODEL + h * DH;
    float* op1 = op0 + 8 * DMODEL;
#pragma unroll
    for (int nt = 0; nt < 8; nt++) {
        *(float2*)&op0[nt * 8 + t4 * 2] = make_float2(co[nt][0] * inv0, co[nt][1] * inv0);
        *(float2*)&op1[nt * 8 + t4 * 2] = make_float2(co[nt][2] * inv1, co[nt][3] * inv1);
    }
}

// ---------------------------------------------------------------------------
extern "C" void kernel_launch(void* const* d_in, const int* in_sizes, int n_in,
                              void* d_out, int out_size)
{
    const float* x    = (const float*)d_in[0];
    const float* mask = (const float*)d_in[1];
    const float* wqkv = (const float*)d_in[2];
    const float* wout = (const float*)d_in[3];
    const float* bout = (const float*)d_in[4];
    float* out = (float*)d_out;

    (void)in_sizes; (void)n_in; (void)out_size;

    static bool attr_done = false;
    if (!attr_done) {
        cudaFuncSetAttribute(mma_gemm<0>, cudaFuncAttributeMaxDynamicSharedMemorySize, GEMM_SMEM);
        cudaFuncSetAttribute(mma_gemm<1>, cudaFuncAttributeMaxDynamicSharedMemorySize, GEMM_SMEM);
        cudaFuncSetAttribute(flash_mma, cudaFuncAttributeMaxDynamicSharedMemorySize, FLASH_SMEM);
        attr_done = true;
    }

    // 1) QKV projection (tf32 mma.sync + cp.async), scattered head-major
    mma_gemm<0><<<dim3((3 * DMODEL) / 128, (BATCH * SEQ) / 128), 256, GEMM_SMEM>>>(
        x, wqkv, nullptr, nullptr, BATCH * SEQ, 3 * DMODEL, DMODEL);

    // 2) flash attention (tf32 mma.sync + cp.async double buffer)
    flash_mma<<<dim3(SEQ / 64, BATCH * NH), 128, FLASH_SMEM>>>(mask);

    // 3) output projection + bias (tf32 mma.sync + cp.async)
    mma_gemm<1><<<dim3(DMODEL / 128, (BATCH * SEQ) / 128), 256, GEMM_SMEM>>>(
        nullptr, wout, bout, out, BATCH * SEQ, DMODEL, DMODEL);
}